// round 3
// baseline (speedup 1.0000x reference)
#include <cuda_runtime.h>
#include <cstdint>

#define BATCH 8
#define HEIGHT 256
#define WIDTH 256
#define HID 128
#define INC 6
#define OUTC 6

// Padded row: [0,1] = left zero pads, [2..257] = x=0..255, [258] = right pad, [259] unused.
// Pixel x maps to index m = x + 2, so even x -> even m -> 8B-aligned float2.
#define ROWP 260

typedef unsigned long long ull;

// Ping-pong intermediate activation buffers (NCHW fp32)
__device__ float g_buf1[(size_t)BATCH * HID * HEIGHT * WIDTH];
__device__ float g_buf2[(size_t)BATCH * HID * HEIGHT * WIDTH];

__device__ __forceinline__ ull pack2(float a, float b) {
    ull r; asm("mov.b64 %0, {%1, %2};" : "=l"(r) : "f"(a), "f"(b)); return r;
}
__device__ __forceinline__ void unpack2(ull v, float& a, float& b) {
    asm("mov.b64 {%0, %1}, %2;" : "=f"(a), "=f"(b) : "l"(v));
}
// Packed dual fp32 FMA — the only way to reach full fp32 rate on sm_103a.
__device__ __forceinline__ ull fma2(ull a, ull b, ull c) {
    ull d; asm("fma.rn.f32x2 %0, %1, %2, %3;" : "=l"(d) : "l"(a), "l"(b), "l"(c)); return d;
}

// ---------------------------------------------------------------------------
// Conv: IC -> 128 channels, 5-point cross stencil, optional ReLU. f32x2 math.
// Block = (b, y). 256 threads = 8 warps; warp = 16-oc group.
// Lane owns 4 pixel PAIRS at x = 2*(lane + 32*i), i in [0,4).
// Weights staged duplicated ({w,w}) so one LDS.64 broadcast feeds FMA2.
// ---------------------------------------------------------------------------
template <int IC, int CHUNK, bool RELU>
__global__ void __launch_bounds__(256, 1)
conv_to128(const float* __restrict__ in, const float* __restrict__ wgt,
           const float* __restrict__ bias, float* __restrict__ out)
{
    extern __shared__ float sm[];
    float* ish = sm;                        // [CHUNK][3][ROWP]
    float* wsh = sm + CHUNK * 3 * ROWP;     // [CHUNK][128][5] duplicated pairs

    const int b = blockIdx.x / HEIGHT;
    const int y = blockIdx.x % HEIGHT;
    const int lane = threadIdx.x & 31;
    const int warp = threadIdx.x >> 5;      // 0..7 -> oc group of 16

    ull acc[16][4];
#pragma unroll
    for (int o = 0; o < 16; ++o)
#pragma unroll
        for (int i = 0; i < 4; ++i) acc[o][i] = 0ull;

    for (int c0 = 0; c0 < IC; c0 += CHUNK) {
        __syncthreads();
        // --- stage input rows y-1, y, y+1 for CHUNK channels (zero-padded) ---
        for (int idx = threadIdx.x; idx < CHUNK * 3 * ROWP; idx += 256) {
            int icl = idx / (3 * ROWP);
            int rem = idx - icl * (3 * ROWP);
            int r = rem / ROWP;
            int j = rem - r * ROWP;
            int yy = y + r - 1;
            int xx = j - 2;
            float v = 0.f;
            if ((unsigned)yy < HEIGHT && (unsigned)xx < WIDTH)
                v = in[(((size_t)b * IC + (c0 + icl)) * HEIGHT + yy) * WIDTH + xx];
            ish[idx] = v;
        }
        // --- stage weights duplicated: wsh[((icl*128+oc)*5+t)*2 + {0,1}] ---
        for (int idx = threadIdx.x; idx < CHUNK * 128 * 5; idx += 256) {
            int icl = idx / (128 * 5);
            int rem = idx - icl * (128 * 5);
            int oc = rem / 5;
            int t = rem - oc * 5;
            float w = wgt[((size_t)oc * IC + (c0 + icl)) * 5 + t];
            wsh[idx * 2 + 0] = w;
            wsh[idx * 2 + 1] = w;
        }
        __syncthreads();

#pragma unroll 1
        for (int icl = 0; icl < CHUNK; ++icl) {
            const float* rowb = &ish[icl * 3 * ROWP];
            ull top[4], cen[4], bot[4], lef[4], rig[4];
#pragma unroll
            for (int i = 0; i < 4; ++i) {
                int m = 2 + 2 * (lane + 32 * i);
                float2 t = *reinterpret_cast<const float2*>(rowb + m);
                float2 c = *reinterpret_cast<const float2*>(rowb + ROWP + m);
                float2 d = *reinterpret_cast<const float2*>(rowb + 2 * ROWP + m);
                float ll = rowb[ROWP + m - 1];
                float rr = rowb[ROWP + m + 2];
                top[i] = pack2(t.x, t.y);
                cen[i] = pack2(c.x, c.y);
                bot[i] = pack2(d.x, d.y);
                lef[i] = pack2(ll, c.x);
                rig[i] = pack2(c.y, rr);
            }
            const ull* wp = reinterpret_cast<const ull*>(wsh) +
                            ((size_t)icl * 128 + warp * 16) * 5;
#pragma unroll
            for (int o = 0; o < 16; ++o) {
                ull w0 = wp[o * 5 + 0];
                ull w1 = wp[o * 5 + 1];
                ull w2 = wp[o * 5 + 2];
                ull w3 = wp[o * 5 + 3];
                ull w4 = wp[o * 5 + 4];
#pragma unroll
                for (int i = 0; i < 4; ++i) {
                    ull s = acc[o][i];
                    s = fma2(w0, cen[i], s);
                    s = fma2(w1, top[i], s);
                    s = fma2(w2, bot[i], s);
                    s = fma2(w3, lef[i], s);
                    s = fma2(w4, rig[i], s);
                    acc[o][i] = s;
                }
            }
        }
    }

    // --- epilogue: bias (+ReLU) and store as float2 ---
#pragma unroll
    for (int o = 0; o < 16; ++o) {
        int oc = warp * 16 + o;
        float bv = bias[oc];
#pragma unroll
        for (int i = 0; i < 4; ++i) {
            float v0, v1;
            unpack2(acc[o][i], v0, v1);
            v0 += bv; v1 += bv;
            if (RELU) { v0 = fmaxf(v0, 0.f); v1 = fmaxf(v1, 0.f); }
            int x = 2 * (lane + 32 * i);
            float2 st; st.x = v0; st.y = v1;
            *reinterpret_cast<float2*>(
                &out[(((size_t)b * 128 + oc) * HEIGHT + y) * WIDTH + x]) = st;
        }
    }
}

// ---------------------------------------------------------------------------
// Final layer: 128 -> 6 channels, no ReLU, f32x2 math.
// Block = 8-row band: warp w handles row y0 + w. Thread: 6 oc x 4 pairs.
// ---------------------------------------------------------------------------
__global__ void __launch_bounds__(256, 1)
conv_last(const float* __restrict__ in, const float* __restrict__ wgt,
          const float* __restrict__ bias, float* __restrict__ out)
{
    extern __shared__ float sm[];
    float* ish = sm;                   // [8][10][ROWP]
    float* wsh = sm + 8 * 10 * ROWP;   // [128][6][5] duplicated pairs

    const int b = blockIdx.x / 32;
    const int y0 = (blockIdx.x % 32) * 8;
    const int lane = threadIdx.x & 31;
    const int warp = threadIdx.x >> 5;   // row within band
    const int y = y0 + warp;

    // preload all weights duplicated: wsh[((ic*6+oc)*5+t)*2 + {0,1}]
    for (int idx = threadIdx.x; idx < 128 * 6 * 5; idx += 256) {
        int ic = idx / 30;
        int rem = idx - ic * 30;
        int oc = rem / 5;
        int t = rem - oc * 5;
        float w = wgt[((size_t)oc * 128 + ic) * 5 + t];
        wsh[idx * 2 + 0] = w;
        wsh[idx * 2 + 1] = w;
    }

    ull acc[6][4];
#pragma unroll
    for (int o = 0; o < 6; ++o)
#pragma unroll
        for (int i = 0; i < 4; ++i) acc[o][i] = 0ull;

    for (int c0 = 0; c0 < 128; c0 += 8) {
        __syncthreads();
        // stage rows y0-1 .. y0+8 for 8 channels
        for (int idx = threadIdx.x; idx < 8 * 10 * ROWP; idx += 256) {
            int icl = idx / (10 * ROWP);
            int rem = idx - icl * (10 * ROWP);
            int r = rem / ROWP;
            int j = rem - r * ROWP;
            int yy = y0 - 1 + r;
            int xx = j - 2;
            float v = 0.f;
            if ((unsigned)yy < HEIGHT && (unsigned)xx < WIDTH)
                v = in[(((size_t)b * 128 + (c0 + icl)) * HEIGHT + yy) * WIDTH + xx];
            ish[idx] = v;
        }
        __syncthreads();

#pragma unroll 1
        for (int icl = 0; icl < 8; ++icl) {
            const float* rowb = &ish[icl * 10 * ROWP + warp * ROWP];
            ull top[4], cen[4], bot[4], lef[4], rig[4];
#pragma unroll
            for (int i = 0; i < 4; ++i) {
                int m = 2 + 2 * (lane + 32 * i);
                float2 t = *reinterpret_cast<const float2*>(rowb + m);
                float2 c = *reinterpret_cast<const float2*>(rowb + ROWP + m);
                float2 d = *reinterpret_cast<const float2*>(rowb + 2 * ROWP + m);
                float ll = rowb[ROWP + m - 1];
                float rr = rowb[ROWP + m + 2];
                top[i] = pack2(t.x, t.y);
                cen[i] = pack2(c.x, c.y);
                bot[i] = pack2(d.x, d.y);
                lef[i] = pack2(ll, c.x);
                rig[i] = pack2(c.y, rr);
            }
            const ull* wp = reinterpret_cast<const ull*>(wsh) +
                            (size_t)(c0 + icl) * 30;
#pragma unroll
            for (int o = 0; o < 6; ++o) {
                ull w0 = wp[o * 5 + 0];
                ull w1 = wp[o * 5 + 1];
                ull w2 = wp[o * 5 + 2];
                ull w3 = wp[o * 5 + 3];
                ull w4 = wp[o * 5 + 4];
#pragma unroll
                for (int i = 0; i < 4; ++i) {
                    ull s = acc[o][i];
                    s = fma2(w0, cen[i], s);
                    s = fma2(w1, top[i], s);
                    s = fma2(w2, bot[i], s);
                    s = fma2(w3, lef[i], s);
                    s = fma2(w4, rig[i], s);
                    acc[o][i] = s;
                }
            }
        }
    }

#pragma unroll
    for (int o = 0; o < 6; ++o) {
        float bv = bias[o];
#pragma unroll
        for (int i = 0; i < 4; ++i) {
            float v0, v1;
            unpack2(acc[o][i], v0, v1);
            v0 += bv; v1 += bv;
            int x = 2 * (lane + 32 * i);
            float2 st; st.x = v0; st.y = v1;
            *reinterpret_cast<float2*>(
                &out[(((size_t)b * OUTC + o) * HEIGHT + y) * WIDTH + x]) = st;
        }
    }
}

extern "C" void kernel_launch(void* const* d_in, const int* in_sizes, int n_in,
                              void* d_out, int out_size)
{
    const float* x  = (const float*)d_in[0];
    const float* w1 = (const float*)d_in[1];
    const float* b1 = (const float*)d_in[2];
    const float* w2 = (const float*)d_in[3];
    const float* b2 = (const float*)d_in[4];
    const float* w3 = (const float*)d_in[5];
    const float* b3 = (const float*)d_in[6];
    const float* w4 = (const float*)d_in[7];
    const float* b4 = (const float*)d_in[8];
    float* out = (float*)d_out;

    float *buf1, *buf2;
    cudaGetSymbolAddress((void**)&buf1, g_buf1);
    cudaGetSymbolAddress((void**)&buf2, g_buf2);

    const int smem1 = (INC * 3 * ROWP + INC * 128 * 5 * 2) * 4;    // ~49 KB
    const int smem2 = (16 * 3 * ROWP + 16 * 128 * 5 * 2) * 4;      // ~129 KB
    const int smem4 = (8 * 10 * ROWP + 128 * 6 * 5 * 2) * 4;       // ~111 KB

    cudaFuncSetAttribute(conv_to128<INC, INC, true>,
                         cudaFuncAttributeMaxDynamicSharedMemorySize, smem1);
    cudaFuncSetAttribute(conv_to128<HID, 16, true>,
                         cudaFuncAttributeMaxDynamicSharedMemorySize, smem2);
    cudaFuncSetAttribute(conv_last,
                         cudaFuncAttributeMaxDynamicSharedMemorySize, smem4);

    dim3 grid_by(BATCH * HEIGHT);           // 2048
    dim3 grid_band(BATCH * (HEIGHT / 8));   // 256

    conv_to128<INC, INC, true><<<grid_by, 256, smem1>>>(x,    w1, b1, buf1);
    conv_to128<HID, 16,  true><<<grid_by, 256, smem2>>>(buf1, w2, b2, buf2);
    conv_to128<HID, 16,  true><<<grid_by, 256, smem2>>>(buf2, w3, b3, buf1);
    conv_last<<<grid_band, 256, smem4>>>(buf1, w4, b4, out);
}

// round 4
// speedup vs baseline: 1.0100x; 1.0100x over previous
#include <cuda_runtime.h>
#include <cstdint>

#define BATCH 8
#define HEIGHT 256
#define WIDTH 256
#define HID 128
#define INC 6
#define OUTC 6

// Padded row: [0,1] = left zero pads, [2..257] = x=0..255, [258] = right pad, [259] unused.
// Pixel x maps to index m = x + 2, so even x -> even m -> 8B-aligned float2.
#define ROWP 260

typedef unsigned long long ull;

// Ping-pong intermediate activation buffers (NCHW fp32)
__device__ float g_buf1[(size_t)BATCH * HID * HEIGHT * WIDTH];
__device__ float g_buf2[(size_t)BATCH * HID * HEIGHT * WIDTH];

__device__ __forceinline__ ull pack2(float a, float b) {
    ull r; asm("mov.b64 %0, {%1, %2};" : "=l"(r) : "f"(a), "f"(b)); return r;
}
__device__ __forceinline__ void unpack2(ull v, float& a, float& b) {
    asm("mov.b64 {%0, %1}, %2;" : "=f"(a), "=f"(b) : "l"(v));
}
// Packed dual fp32 FMA — the only way to reach full fp32 rate on sm_103a.
__device__ __forceinline__ ull fma2(ull a, ull b, ull c) {
    ull d; asm("fma.rn.f32x2 %0, %1, %2, %3;" : "=l"(d) : "l"(a), "l"(b), "l"(c)); return d;
}

// ---------------------------------------------------------------------------
// Conv: IC -> 128 channels, 5-point cross stencil, optional ReLU. f32x2 math.
// Block = (b, y). 256 threads = 8 warps; warp = 16-oc group.
// Lane owns 4 pixel PAIRS at x = 2*(lane + 32*i), i in [0,4).
// Weights staged duplicated ({w,w}) so one LDS.64 broadcast feeds FMA2.
// ---------------------------------------------------------------------------
template <int IC, int CHUNK, bool RELU>
__global__ void __launch_bounds__(256, 1)
conv_to128(const float* __restrict__ in, const float* __restrict__ wgt,
           const float* __restrict__ bias, float* __restrict__ out)
{
    extern __shared__ float sm[];
    float* ish = sm;                        // [CHUNK][3][ROWP]
    float* wsh = sm + CHUNK * 3 * ROWP;     // [CHUNK][128][5] duplicated pairs

    const int b = blockIdx.x / HEIGHT;
    const int y = blockIdx.x % HEIGHT;
    const int lane = threadIdx.x & 31;
    const int warp = threadIdx.x >> 5;      // 0..7 -> oc group of 16

    ull acc[16][4];
#pragma unroll
    for (int o = 0; o < 16; ++o)
#pragma unroll
        for (int i = 0; i < 4; ++i) acc[o][i] = 0ull;

    for (int c0 = 0; c0 < IC; c0 += CHUNK) {
        __syncthreads();
        // --- stage input rows y-1, y, y+1 for CHUNK channels (zero-padded) ---
        for (int idx = threadIdx.x; idx < CHUNK * 3 * ROWP; idx += 256) {
            int icl = idx / (3 * ROWP);
            int rem = idx - icl * (3 * ROWP);
            int r = rem / ROWP;
            int j = rem - r * ROWP;
            int yy = y + r - 1;
            int xx = j - 2;
            float v = 0.f;
            if ((unsigned)yy < HEIGHT && (unsigned)xx < WIDTH)
                v = in[(((size_t)b * IC + (c0 + icl)) * HEIGHT + yy) * WIDTH + xx];
            ish[idx] = v;
        }
        // --- stage weights duplicated: wsh[((icl*128+oc)*5+t)*2 + {0,1}] ---
        for (int idx = threadIdx.x; idx < CHUNK * 128 * 5; idx += 256) {
            int icl = idx / (128 * 5);
            int rem = idx - icl * (128 * 5);
            int oc = rem / 5;
            int t = rem - oc * 5;
            float w = wgt[((size_t)oc * IC + (c0 + icl)) * 5 + t];
            wsh[idx * 2 + 0] = w;
            wsh[idx * 2 + 1] = w;
        }
        __syncthreads();

#pragma unroll 1
        for (int icl = 0; icl < CHUNK; ++icl) {
            const float* rowb = &ish[icl * 3 * ROWP];
            ull top[4], cen[4], bot[4], lef[4], rig[4];
#pragma unroll
            for (int i = 0; i < 4; ++i) {
                int m = 2 + 2 * (lane + 32 * i);
                float2 t = *reinterpret_cast<const float2*>(rowb + m);
                float2 c = *reinterpret_cast<const float2*>(rowb + ROWP + m);
                float2 d = *reinterpret_cast<const float2*>(rowb + 2 * ROWP + m);
                float ll = rowb[ROWP + m - 1];
                float rr = rowb[ROWP + m + 2];
                top[i] = pack2(t.x, t.y);
                cen[i] = pack2(c.x, c.y);
                bot[i] = pack2(d.x, d.y);
                lef[i] = pack2(ll, c.x);
                rig[i] = pack2(c.y, rr);
            }
            const ull* wp = reinterpret_cast<const ull*>(wsh) +
                            ((size_t)icl * 128 + warp * 16) * 5;
#pragma unroll
            for (int o = 0; o < 16; ++o) {
                ull w0 = wp[o * 5 + 0];
                ull w1 = wp[o * 5 + 1];
                ull w2 = wp[o * 5 + 2];
                ull w3 = wp[o * 5 + 3];
                ull w4 = wp[o * 5 + 4];
#pragma unroll
                for (int i = 0; i < 4; ++i) {
                    ull s = acc[o][i];
                    s = fma2(w0, cen[i], s);
                    s = fma2(w1, top[i], s);
                    s = fma2(w2, bot[i], s);
                    s = fma2(w3, lef[i], s);
                    s = fma2(w4, rig[i], s);
                    acc[o][i] = s;
                }
            }
        }
    }

    // --- epilogue: bias (+ReLU) and store as float2 ---
#pragma unroll
    for (int o = 0; o < 16; ++o) {
        int oc = warp * 16 + o;
        float bv = bias[oc];
#pragma unroll
        for (int i = 0; i < 4; ++i) {
            float v0, v1;
            unpack2(acc[o][i], v0, v1);
            v0 += bv; v1 += bv;
            if (RELU) { v0 = fmaxf(v0, 0.f); v1 = fmaxf(v1, 0.f); }
            int x = 2 * (lane + 32 * i);
            float2 st; st.x = v0; st.y = v1;
            *reinterpret_cast<float2*>(
                &out[(((size_t)b * 128 + oc) * HEIGHT + y) * WIDTH + x]) = st;
        }
    }
}

// ---------------------------------------------------------------------------
// Final layer: 128 -> 6 channels, no ReLU, f32x2 math.
// Block = 8-row band: warp w handles row y0 + w. Thread: 6 oc x 4 pairs.
// ---------------------------------------------------------------------------
__global__ void __launch_bounds__(256, 1)
conv_last(const float* __restrict__ in, const float* __restrict__ wgt,
          const float* __restrict__ bias, float* __restrict__ out)
{
    extern __shared__ float sm[];
    float* ish = sm;                   // [8][10][ROWP]
    float* wsh = sm + 8 * 10 * ROWP;   // [128][6][5] duplicated pairs

    const int b = blockIdx.x / 32;
    const int y0 = (blockIdx.x % 32) * 8;
    const int lane = threadIdx.x & 31;
    const int warp = threadIdx.x >> 5;   // row within band
    const int y = y0 + warp;

    // preload all weights duplicated: wsh[((ic*6+oc)*5+t)*2 + {0,1}]
    for (int idx = threadIdx.x; idx < 128 * 6 * 5; idx += 256) {
        int ic = idx / 30;
        int rem = idx - ic * 30;
        int oc = rem / 5;
        int t = rem - oc * 5;
        float w = wgt[((size_t)oc * 128 + ic) * 5 + t];
        wsh[idx * 2 + 0] = w;
        wsh[idx * 2 + 1] = w;
    }

    ull acc[6][4];
#pragma unroll
    for (int o = 0; o < 6; ++o)
#pragma unroll
        for (int i = 0; i < 4; ++i) acc[o][i] = 0ull;

    for (int c0 = 0; c0 < 128; c0 += 8) {
        __syncthreads();
        // stage rows y0-1 .. y0+8 for 8 channels
        for (int idx = threadIdx.x; idx < 8 * 10 * ROWP; idx += 256) {
            int icl = idx / (10 * ROWP);
            int rem = idx - icl * (10 * ROWP);
            int r = rem / ROWP;
            int j = rem - r * ROWP;
            int yy = y0 - 1 + r;
            int xx = j - 2;
            float v = 0.f;
            if ((unsigned)yy < HEIGHT && (unsigned)xx < WIDTH)
                v = in[(((size_t)b * 128 + (c0 + icl)) * HEIGHT + yy) * WIDTH + xx];
            ish[idx] = v;
        }
        __syncthreads();

#pragma unroll 1
        for (int icl = 0; icl < 8; ++icl) {
            const float* rowb = &ish[icl * 10 * ROWP + warp * ROWP];
            ull top[4], cen[4], bot[4], lef[4], rig[4];
#pragma unroll
            for (int i = 0; i < 4; ++i) {
                int m = 2 + 2 * (lane + 32 * i);
                float2 t = *reinterpret_cast<const float2*>(rowb + m);
                float2 c = *reinterpret_cast<const float2*>(rowb + ROWP + m);
                float2 d = *reinterpret_cast<const float2*>(rowb + 2 * ROWP + m);
                float ll = rowb[ROWP + m - 1];
                float rr = rowb[ROWP + m + 2];
                top[i] = pack2(t.x, t.y);
                cen[i] = pack2(c.x, c.y);
                bot[i] = pack2(d.x, d.y);
                lef[i] = pack2(ll, c.x);
                rig[i] = pack2(c.y, rr);
            }
            const ull* wp = reinterpret_cast<const ull*>(wsh) +
                            (size_t)(c0 + icl) * 30;
#pragma unroll
            for (int o = 0; o < 6; ++o) {
                ull w0 = wp[o * 5 + 0];
                ull w1 = wp[o * 5 + 1];
                ull w2 = wp[o * 5 + 2];
                ull w3 = wp[o * 5 + 3];
                ull w4 = wp[o * 5 + 4];
#pragma unroll
                for (int i = 0; i < 4; ++i) {
                    ull s = acc[o][i];
                    s = fma2(w0, cen[i], s);
                    s = fma2(w1, top[i], s);
                    s = fma2(w2, bot[i], s);
                    s = fma2(w3, lef[i], s);
                    s = fma2(w4, rig[i], s);
                    acc[o][i] = s;
                }
            }
        }
    }

#pragma unroll
    for (int o = 0; o < 6; ++o) {
        float bv = bias[o];
#pragma unroll
        for (int i = 0; i < 4; ++i) {
            float v0, v1;
            unpack2(acc[o][i], v0, v1);
            v0 += bv; v1 += bv;
            int x = 2 * (lane + 32 * i);
            float2 st; st.x = v0; st.y = v1;
            *reinterpret_cast<float2*>(
                &out[(((size_t)b * OUTC + o) * HEIGHT + y) * WIDTH + x]) = st;
        }
    }
}

extern "C" void kernel_launch(void* const* d_in, const int* in_sizes, int n_in,
                              void* d_out, int out_size)
{
    const float* x  = (const float*)d_in[0];
    const float* w1 = (const float*)d_in[1];
    const float* b1 = (const float*)d_in[2];
    const float* w2 = (const float*)d_in[3];
    const float* b2 = (const float*)d_in[4];
    const float* w3 = (const float*)d_in[5];
    const float* b3 = (const float*)d_in[6];
    const float* w4 = (const float*)d_in[7];
    const float* b4 = (const float*)d_in[8];
    float* out = (float*)d_out;

    float *buf1, *buf2;
    cudaGetSymbolAddress((void**)&buf1, g_buf1);
    cudaGetSymbolAddress((void**)&buf2, g_buf2);

    const int smem1 = (INC * 3 * ROWP + INC * 128 * 5 * 2) * 4;    // ~49 KB
    const int smem2 = (16 * 3 * ROWP + 16 * 128 * 5 * 2) * 4;      // ~129 KB
    const int smem4 = (8 * 10 * ROWP + 128 * 6 * 5 * 2) * 4;       // ~111 KB

    cudaFuncSetAttribute(conv_to128<INC, INC, true>,
                         cudaFuncAttributeMaxDynamicSharedMemorySize, smem1);
    cudaFuncSetAttribute(conv_to128<HID, 16, true>,
                         cudaFuncAttributeMaxDynamicSharedMemorySize, smem2);
    cudaFuncSetAttribute(conv_last,
                         cudaFuncAttributeMaxDynamicSharedMemorySize, smem4);

    dim3 grid_by(BATCH * HEIGHT);           // 2048
    dim3 grid_band(BATCH * (HEIGHT / 8));   // 256

    conv_to128<INC, INC, true><<<grid_by, 256, smem1>>>(x,    w1, b1, buf1);
    conv_to128<HID, 16,  true><<<grid_by, 256, smem2>>>(buf1, w2, b2, buf2);
    conv_to128<HID, 16,  true><<<grid_by, 256, smem2>>>(buf2, w3, b3, buf1);
    conv_last<<<grid_band, 256, smem4>>>(buf1, w4, b4, out);
}

// round 7
// speedup vs baseline: 1.9606x; 1.9412x over previous
#include <cuda_runtime.h>
#include <cuda_bf16.h>
#include <cstdint>

typedef unsigned int u32; typedef unsigned short u16; typedef unsigned long long u64;

#define BB 8
#define HH 256
#define WW 256
#define HID 128

// NHWC intermediate activations
__device__ float g_act1[(size_t)BB*HH*WW*HID];
__device__ float g_act2[(size_t)BB*HH*WW*HID];
// bf16 split weights: L1 @0 [128][5][8], L2 @5120 [128][5][128], L3 @87040
__device__ u16 g_wh[168960];
__device__ u16 g_wl[168960];

static __device__ __forceinline__ u32 s2u(const void* p){
    u32 a; asm("{ .reg .u64 t; cvta.to.shared.u64 t, %1; cvt.u32.u64 %0, t; }":"=r"(a):"l"(p)); return a;}

static __device__ __forceinline__ void ldm4(u32* r, u32 addr){
    asm volatile("ldmatrix.sync.aligned.m8n8.x4.shared.b16 {%0,%1,%2,%3}, [%4];"
        : "=r"(r[0]),"=r"(r[1]),"=r"(r[2]),"=r"(r[3]) : "r"(addr));}

static __device__ __forceinline__ void mma16816(float* d, const u32* a, const u32* b){
    asm volatile("mma.sync.aligned.m16n8k16.row.col.f32.bf16.bf16.f32 "
        "{%0,%1,%2,%3}, {%4,%5,%6,%7}, {%8,%9}, {%0,%1,%2,%3};"
        : "+f"(d[0]),"+f"(d[1]),"+f"(d[2]),"+f"(d[3])
        : "r"(a[0]),"r"(a[1]),"r"(a[2]),"r"(a[3]), "r"(b[0]),"r"(b[1]));}

static __device__ __forceinline__ void split_bf16(float v, u16& h, u16& l){
    __nv_bfloat16 hb = __float2bfloat16(v);
    float r = v - __bfloat162float(hb);
    __nv_bfloat16 lb = __float2bfloat16(r);
    h = __bfloat16_as_ushort(hb);
    l = __bfloat16_as_ushort(lb);
}

__constant__ int c_dx[5] = {0, 0, 0, -1, 1};
__constant__ int c_dy[5] = {0, -1, 1, 0, 0};

// ---------------------------------------------------------------------------
// prep: split weights into bf16 hi/lo, layout [oc][tap][ic]
// ---------------------------------------------------------------------------
__global__ void prep(const float* __restrict__ w1, const float* __restrict__ w2,
                     const float* __restrict__ w3)
{
    int i = blockIdx.x * 256 + threadIdx.x;
    if (i >= 168960) return;
    float v;
    if (i < 5120) {                         // L1: [oc][t][8], ic<6 real
        int oc = i / 40, rem = i % 40, t = rem / 8, ic = rem % 8;
        v = (ic < 6) ? w1[(oc*6 + ic)*5 + t] : 0.f;
    } else if (i < 87040) {                 // L2: [oc][t][128]
        int j = i - 5120;
        int oc = j / 640, rem = j % 640, t = rem / 128, ic = rem % 128;
        v = w2[(oc*128 + ic)*5 + t];
    } else {                                // L3
        int j = i - 87040;
        int oc = j / 640, rem = j % 640, t = rem / 128, ic = rem % 128;
        v = w3[(oc*128 + ic)*5 + t];
    }
    u16 h, l; split_bf16(v, h, l);
    g_wh[i] = h; g_wl[i] = l;
}

// ---------------------------------------------------------------------------
// conv_mma: one layer -> 128 oc, NHWC out, ReLU.
// D[128oc,128px] = W[128, 5*IC] * B[5*IC, 128px], B gathered with tap shifts.
// Block = (b, y, x-half). 8 warps: wm in {0,1} (64 oc), wn in {0..3} (32 px).
// bf16 3-pass split: Ah*Bh + Al*Bh + Ah*Bl, fp32 accum.
// ---------------------------------------------------------------------------
template <int ICW, int CHUNKS, bool NCHW_IN>
__global__ void __launch_bounds__(256, 1)
conv_mma(const float* __restrict__ in, const u16* __restrict__ wh,
         const u16* __restrict__ wl, const float* __restrict__ bias,
         float* __restrict__ out)
{
    constexpr int KC  = (5*ICW + 15) & ~15;   // 160 (ICW=32) / 48 (ICW=8)
    constexpr int STR = KC*2 + 16;            // row stride bytes: 336 / 112
    constexpr int ICS = NCHW_IN ? 8 : 128;    // weight ic extent in g_wh

    extern __shared__ char smc[];
    char* Ah = smc;
    char* Al = Ah + 128*STR;
    char* Bh = Al + 128*STR;
    char* Bl = Bh + 128*STR;
    const u32 sbAh = s2u(Ah), sbAl = s2u(Al), sbBh = s2u(Bh), sbBl = s2u(Bl);

    const int tid = threadIdx.x;
    const int warp = tid >> 5, lane = tid & 31;
    const int wm = warp >> 2, wn = warp & 3;

    const int bi = blockIdx.x;
    const int b  = bi >> 9;
    const int y  = (bi >> 1) & 255;
    const int x0 = (bi & 1) * 128;

    // zero pad region for ICW=8 (K padded 40->48, ic padded 6->8)
    if (ICW == 8) {
        for (int i = tid; i < 4*128*STR/16; i += 256)
            reinterpret_cast<uint4*>(smc)[i] = make_uint4(0,0,0,0);
    }

    float D[4][4][4];
#pragma unroll
    for (int mt = 0; mt < 4; ++mt)
#pragma unroll
        for (int nt = 0; nt < 4; ++nt)
#pragma unroll
            for (int r = 0; r < 4; ++r) D[mt][nt][r] = 0.f;

    // per-thread ldmatrix address offsets
    const u32 aoff = (u32)((wm*64 + (lane & 15))*STR + (lane >> 4)*16);
    const u32 boff = (u32)((wn*32 + ((lane >> 4) & 1)*8 + (lane & 7))*STR
                           + ((lane >> 3) & 1)*16);

    for (int c = 0; c < CHUNKS; ++c) {
        __syncthreads();
        const int c0 = c * ICW;

        // ---- stage A: weights [128 oc][5 tap][ICW ic] hi/lo ----
        for (int idx = tid; idx < 128*5*(ICW/8); idx += 256) {
            int oc = idx / (5*(ICW/8));
            int rem = idx % (5*(ICW/8));
            int t = rem / (ICW/8), q = rem % (ICW/8);
            size_t g = (size_t)(oc*5 + t)*ICS + c0 + q*8;
            uint4 vh = *reinterpret_cast<const uint4*>(&wh[g]);
            uint4 vl = *reinterpret_cast<const uint4*>(&wl[g]);
            int d = oc*STR + (t*ICW + q*8)*2;
            *reinterpret_cast<uint4*>(Ah + d) = vh;
            *reinterpret_cast<uint4*>(Al + d) = vl;
        }

        // ---- stage B: gathered, shifted activations hi/lo ----
        if (NCHW_IN) {
            for (int idx = tid; idx < 128*5*6; idx += 256) {
                int n = idx / 30, rem = idx % 30;
                int t = rem / 6, ic = rem % 6;
                int yy = y + c_dy[t], xx = x0 + n + c_dx[t];
                float v = 0.f;
                if ((unsigned)yy < HH && (unsigned)xx < WW)
                    v = in[(((size_t)b*6 + ic)*HH + yy)*WW + xx];
                u16 h, l; split_bf16(v, h, l);
                int d = n*STR + (t*8 + ic)*2;
                *reinterpret_cast<u16*>(Bh + d) = h;
                *reinterpret_cast<u16*>(Bl + d) = l;
            }
        } else {
            for (int idx = tid; idx < 128*5*(ICW/4); idx += 256) {
                int n = idx / (5*(ICW/4));
                int rem = idx % (5*(ICW/4));
                int t = rem / (ICW/4), q = rem % (ICW/4);
                int yy = y + c_dy[t], xx = x0 + n + c_dx[t];
                float4 v = make_float4(0,0,0,0);
                if ((unsigned)yy < HH && (unsigned)xx < WW)
                    v = *reinterpret_cast<const float4*>(
                        &in[(((size_t)b*HH + yy)*WW + xx)*HID + c0 + q*4]);
                u16 h0,h1,h2,h3,l0,l1,l2,l3;
                split_bf16(v.x,h0,l0); split_bf16(v.y,h1,l1);
                split_bf16(v.z,h2,l2); split_bf16(v.w,h3,l3);
                uint2 hv, lv;
                hv.x = (u32)h0 | ((u32)h1<<16); hv.y = (u32)h2 | ((u32)h3<<16);
                lv.x = (u32)l0 | ((u32)l1<<16); lv.y = (u32)l2 | ((u32)l3<<16);
                int d = n*STR + (t*ICW + q*4)*2;
                *reinterpret_cast<uint2*>(Bh + d) = hv;
                *reinterpret_cast<uint2*>(Bl + d) = lv;
            }
        }
        __syncthreads();

        // ---- mma over K chunk ----
#pragma unroll 1
        for (int ks = 0; ks < KC/16; ++ks) {
            const u32 kb2 = (u32)(ks * 32);   // kb*2 bytes
            u32 ah[4][4], al[4][4], bh[2][4], bl[2][4];
#pragma unroll
            for (int mt = 0; mt < 4; ++mt) {
                ldm4(ah[mt], sbAh + aoff + mt*16*STR + kb2);
                ldm4(al[mt], sbAl + aoff + mt*16*STR + kb2);
            }
#pragma unroll
            for (int g = 0; g < 2; ++g) {
                ldm4(bh[g], sbBh + boff + g*16*STR + kb2);
                ldm4(bl[g], sbBl + boff + g*16*STR + kb2);
            }
#pragma unroll
            for (int mt = 0; mt < 4; ++mt)
#pragma unroll
                for (int nt = 0; nt < 4; ++nt) {
                    const u32* bhp = &bh[nt>>1][(nt&1)*2];
                    const u32* blp = &bl[nt>>1][(nt&1)*2];
                    mma16816(D[mt][nt], ah[mt], bhp);
                    mma16816(D[mt][nt], al[mt], bhp);
                    mma16816(D[mt][nt], ah[mt], blp);
                }
        }
    }

    // ---- epilogue: bias + ReLU, NHWC store ----
    float bias2[4][2];
#pragma unroll
    for (int mt = 0; mt < 4; ++mt) {
        bias2[mt][0] = bias[wm*64 + mt*16 + (lane>>2)];
        bias2[mt][1] = bias[wm*64 + mt*16 + (lane>>2) + 8];
    }
    float* ob = &out[(((size_t)b*HH + y)*WW + x0)*HID];
#pragma unroll
    for (int mt = 0; mt < 4; ++mt)
#pragma unroll
        for (int nt = 0; nt < 4; ++nt)
#pragma unroll
            for (int r = 0; r < 4; ++r) {
                int m = wm*64 + mt*16 + (lane>>2) + ((r>>1)&1)*8;
                int n = wn*32 + nt*8 + (lane&3)*2 + (r&1);
                float v = D[mt][nt][r] + bias2[mt][(r>>1)&1];
                v = fmaxf(v, 0.f);
                ob[(size_t)n*HID + m] = v;
            }
}

// ---------------------------------------------------------------------------
// Final layer: NHWC 128 -> NCHW 6, SIMT. Block=(b,y), thread=pixel.
// ---------------------------------------------------------------------------
__global__ void __launch_bounds__(256, 1)
conv4(const float* __restrict__ in, const float* __restrict__ wgt,
      const float* __restrict__ bias, float* __restrict__ out)
{
    extern __shared__ float sm4[];
    float* ash = sm4;              // [3][258] x 33 floats (32 ic + pad)
    float* wsh = sm4 + 3*258*33;   // [6][128][5]

    const int b = blockIdx.x >> 8;
    const int y = blockIdx.x & 255;
    const int px = threadIdx.x;

    for (int i = threadIdx.x; i < 3840; i += 256) wsh[i] = wgt[i];

    float acc[6];
#pragma unroll
    for (int o = 0; o < 6; ++o) acc[o] = 0.f;

    for (int c = 0; c < 4; ++c) {
        __syncthreads();
        for (int idx = threadIdx.x; idx < 3*258*8; idx += 256) {
            int r = idx / (258*8), rem = idx % (258*8);
            int s = rem >> 3, kq = rem & 7;
            int yy = y + r - 1, xx = s - 1;
            float4 v = make_float4(0,0,0,0);
            if ((unsigned)yy < HH && (unsigned)xx < WW)
                v = *reinterpret_cast<const float4*>(
                    &in[(((size_t)b*HH + yy)*WW + xx)*HID + c*32 + kq*4]);
            float* d = &ash[(r*258 + s)*33 + kq*4];
            d[0] = v.x; d[1] = v.y; d[2] = v.z; d[3] = v.w;
        }
        __syncthreads();

        const float* au = &ash[(0*258 + px + 1)*33];
        const float* ac = &ash[(1*258 + px + 1)*33];
        const float* ad = &ash[(2*258 + px + 1)*33];
        const float* al = &ash[(1*258 + px + 0)*33];
        const float* ar = &ash[(1*258 + px + 2)*33];
#pragma unroll 4
        for (int k = 0; k < 32; ++k) {
            float vc = ac[k], vu = au[k], vd = ad[k], vl = al[k], vr = ar[k];
            const float* wp = &wsh[(c*32 + k)*5];
#pragma unroll
            for (int o = 0; o < 6; ++o) {
                const float* w = wp + o*640;
                float s = acc[o];
                s = fmaf(w[0], vc, s);
                s = fmaf(w[1], vu, s);
                s = fmaf(w[2], vd, s);
                s = fmaf(w[3], vl, s);
                s = fmaf(w[4], vr, s);
                acc[o] = s;
            }
        }
    }

#pragma unroll
    for (int o = 0; o < 6; ++o)
        out[(((size_t)b*6 + o)*HH + y)*WW + px] = acc[o] + bias[o];
}

extern "C" void kernel_launch(void* const* d_in, const int* in_sizes, int n_in,
                              void* d_out, int out_size)
{
    const float* x  = (const float*)d_in[0];
    const float* w1 = (const float*)d_in[1];
    const float* b1 = (const float*)d_in[2];
    const float* w2 = (const float*)d_in[3];
    const float* b2 = (const float*)d_in[4];
    const float* w3 = (const float*)d_in[5];
    const float* b3 = (const float*)d_in[6];
    const float* w4 = (const float*)d_in[7];
    const float* b4 = (const float*)d_in[8];
    float* out = (float*)d_out;

    float *act1, *act2; u16 *wh, *wl;
    cudaGetSymbolAddress((void**)&act1, g_act1);
    cudaGetSymbolAddress((void**)&act2, g_act2);
    cudaGetSymbolAddress((void**)&wh,   g_wh);
    cudaGetSymbolAddress((void**)&wl,   g_wl);

    const int smemL1  = 4*128*112;    // 57344
    const int smemMid = 4*128*336;    // 172032
    const int smem4   = (3*258*33 + 3840) * 4;

    cudaFuncSetAttribute(conv_mma<8, 1, true>,
                         cudaFuncAttributeMaxDynamicSharedMemorySize, smemL1);
    cudaFuncSetAttribute(conv_mma<32, 4, false>,
                         cudaFuncAttributeMaxDynamicSharedMemorySize, smemMid);
    cudaFuncSetAttribute(conv4,
                         cudaFuncAttributeMaxDynamicSharedMemorySize, smem4);

    prep<<<660, 256>>>(w1, w2, w3);
    conv_mma<8, 1, true ><<<BB*HH*2, 256, smemL1 >>>(x,    wh,         wl,         b1, act1);
    conv_mma<32, 4, false><<<BB*HH*2, 256, smemMid>>>(act1, wh + 5120,  wl + 5120,  b2, act2);
    conv_mma<32, 4, false><<<BB*HH*2, 256, smemMid>>>(act2, wh + 87040, wl + 87040, b3, act1);
    conv4<<<BB*HH, 256, smem4>>>(act1, w4, b4, out);
}

// round 10
// speedup vs baseline: 2.6286x; 1.3407x over previous
#include <cuda_runtime.h>
#include <cuda_bf16.h>
#include <cstdint>

typedef unsigned int u32; typedef unsigned short u16; typedef unsigned long long u64;

#define BB 8
#define HH 256
#define WW 256
#define HID 128

// NHWC intermediate activations
__device__ float g_act1[(size_t)BB*HH*WW*HID];
__device__ float g_act2[(size_t)BB*HH*WW*HID];
// bf16 split weights: L1 @0 [128][5][8], L2 @5120 [128][5][128], L3 @87040
__device__ u16 g_wh[168960];
__device__ u16 g_wl[168960];

static __device__ __forceinline__ u32 s2u(const void* p){
    u32 a; asm("{ .reg .u64 t; cvta.to.shared.u64 t, %1; cvt.u32.u64 %0, t; }":"=r"(a):"l"(p)); return a;}

static __device__ __forceinline__ void ldm4(u32* r, u32 addr){
    asm volatile("ldmatrix.sync.aligned.m8n8.x4.shared.b16 {%0,%1,%2,%3}, [%4];"
        : "=r"(r[0]),"=r"(r[1]),"=r"(r[2]),"=r"(r[3]) : "r"(addr));}

static __device__ __forceinline__ void mma16816(float* d, const u32* a, const u32* b){
    asm volatile("mma.sync.aligned.m16n8k16.row.col.f32.bf16.bf16.f32 "
        "{%0,%1,%2,%3}, {%4,%5,%6,%7}, {%8,%9}, {%0,%1,%2,%3};"
        : "+f"(d[0]),"+f"(d[1]),"+f"(d[2]),"+f"(d[3])
        : "r"(a[0]),"r"(a[1]),"r"(a[2]),"r"(a[3]), "r"(b[0]),"r"(b[1]));}

static __device__ __forceinline__ void split_bf16(float v, u16& h, u16& l){
    __nv_bfloat16 hb = __float2bfloat16(v);
    float r = v - __bfloat162float(hb);
    __nv_bfloat16 lb = __float2bfloat16(r);
    h = __bfloat16_as_ushort(hb);
    l = __bfloat16_as_ushort(lb);
}

__constant__ int c_dx[5] = {0, 0, 0, -1, 1};
__constant__ int c_dy[5] = {0, -1, 1, 0, 0};

// ---------------------------------------------------------------------------
// prep: split weights into bf16 hi/lo, layout [oc][tap][ic]
// ---------------------------------------------------------------------------
__global__ void prep(const float* __restrict__ w1, const float* __restrict__ w2,
                     const float* __restrict__ w3)
{
    int i = blockIdx.x * 256 + threadIdx.x;
    if (i >= 168960) return;
    float v;
    if (i < 5120) {                         // L1: [oc][t][8], ic<6 real
        int oc = i / 40, rem = i % 40, t = rem / 8, ic = rem % 8;
        v = (ic < 6) ? w1[(oc*6 + ic)*5 + t] : 0.f;
    } else if (i < 87040) {                 // L2: [oc][t][128]
        int j = i - 5120;
        int oc = j / 640, rem = j % 640, t = rem / 128, ic = rem % 128;
        v = w2[(oc*128 + ic)*5 + t];
    } else {                                // L3
        int j = i - 87040;
        int oc = j / 640, rem = j % 640, t = rem / 128, ic = rem % 128;
        v = w3[(oc*128 + ic)*5 + t];
    }
    u16 h, l; split_bf16(v, h, l);
    g_wh[i] = h; g_wl[i] = l;
}

// ---------------------------------------------------------------------------
// conv_mma: one layer -> 128 oc, NHWC out, ReLU.
// D[128oc,128px] = W[128, 5*IC] * B[5*IC, 128px], B gathered with tap shifts.
// Block = (b, y, x-half). 8 warps: wm in {0,1} (64 oc), wn in {0..3} (32 px).
// bf16 3-pass split: Ah*Bh + Al*Bh + Ah*Bl, fp32 accum.
// ICW=16 -> 90KB smem; launch_bounds(256,2) -> 2 CTAs/SM for staging/MMA overlap.
// ---------------------------------------------------------------------------
template <int ICW, int CHUNKS, bool NCHW_IN, int MINB>
__global__ void __launch_bounds__(256, MINB)
conv_mma(const float* __restrict__ in, const u16* __restrict__ wh,
         const u16* __restrict__ wl, const float* __restrict__ bias,
         float* __restrict__ out)
{
    constexpr int KC  = (5*ICW + 15) & ~15;   // 80 (ICW=16) / 48 (ICW=8)
    constexpr int STR = KC*2 + 16;            // row stride bytes: 176 / 112
    constexpr int ICS = NCHW_IN ? 8 : 128;    // weight ic extent in g_wh

    extern __shared__ char smc[];
    char* Ah = smc;
    char* Al = Ah + 128*STR;
    char* Bh = Al + 128*STR;
    char* Bl = Bh + 128*STR;
    const u32 sbAh = s2u(Ah), sbAl = s2u(Al), sbBh = s2u(Bh), sbBl = s2u(Bl);

    const int tid = threadIdx.x;
    const int warp = tid >> 5, lane = tid & 31;
    const int wm = warp >> 2, wn = warp & 3;

    const int bi = blockIdx.x;
    const int b  = bi >> 9;
    const int y  = (bi >> 1) & 255;
    const int x0 = (bi & 1) * 128;

    // zero pad region for ICW=8 (K padded 40->48, ic padded 6->8)
    if (ICW == 8) {
        for (int i = tid; i < 4*128*STR/16; i += 256)
            reinterpret_cast<uint4*>(smc)[i] = make_uint4(0,0,0,0);
    }

    float D[4][4][4];
#pragma unroll
    for (int mt = 0; mt < 4; ++mt)
#pragma unroll
        for (int nt = 0; nt < 4; ++nt)
#pragma unroll
            for (int r = 0; r < 4; ++r) D[mt][nt][r] = 0.f;

    // per-thread ldmatrix address offsets
    const u32 aoff = (u32)((wm*64 + (lane & 15))*STR + (lane >> 4)*16);
    const u32 boff = (u32)((wn*32 + ((lane >> 4) & 1)*8 + (lane & 7))*STR
                           + ((lane >> 3) & 1)*16);

    for (int c = 0; c < CHUNKS; ++c) {
        __syncthreads();
        const int c0 = c * ICW;

        // ---- stage A: weights [128 oc][5 tap][ICW ic] hi/lo ----
        for (int idx = tid; idx < 128*5*(ICW/8); idx += 256) {
            int oc = idx / (5*(ICW/8));
            int rem = idx % (5*(ICW/8));
            int t = rem / (ICW/8), q = rem % (ICW/8);
            size_t g = (size_t)(oc*5 + t)*ICS + c0 + q*8;
            uint4 vh = *reinterpret_cast<const uint4*>(&wh[g]);
            uint4 vl = *reinterpret_cast<const uint4*>(&wl[g]);
            int d = oc*STR + (t*ICW + q*8)*2;
            *reinterpret_cast<uint4*>(Ah + d) = vh;
            *reinterpret_cast<uint4*>(Al + d) = vl;
        }

        // ---- stage B: gathered, shifted activations hi/lo ----
        if (NCHW_IN) {
            for (int idx = tid; idx < 128*5*6; idx += 256) {
                int n = idx / 30, rem = idx % 30;
                int t = rem / 6, ic = rem % 6;
                int yy = y + c_dy[t], xx = x0 + n + c_dx[t];
                float v = 0.f;
                if ((unsigned)yy < HH && (unsigned)xx < WW)
                    v = in[(((size_t)b*6 + ic)*HH + yy)*WW + xx];
                u16 h, l; split_bf16(v, h, l);
                int d = n*STR + (t*8 + ic)*2;
                *reinterpret_cast<u16*>(Bh + d) = h;
                *reinterpret_cast<u16*>(Bl + d) = l;
            }
        } else {
            for (int idx = tid; idx < 128*5*(ICW/4); idx += 256) {
                int n = idx / (5*(ICW/4));
                int rem = idx % (5*(ICW/4));
                int t = rem / (ICW/4), q = rem % (ICW/4);
                int yy = y + c_dy[t], xx = x0 + n + c_dx[t];
                float4 v = make_float4(0,0,0,0);
                if ((unsigned)yy < HH && (unsigned)xx < WW)
                    v = *reinterpret_cast<const float4*>(
                        &in[(((size_t)b*HH + yy)*WW + xx)*HID + c0 + q*4]);
                u16 h0,h1,h2,h3,l0,l1,l2,l3;
                split_bf16(v.x,h0,l0); split_bf16(v.y,h1,l1);
                split_bf16(v.z,h2,l2); split_bf16(v.w,h3,l3);
                uint2 hv, lv;
                hv.x = (u32)h0 | ((u32)h1<<16); hv.y = (u32)h2 | ((u32)h3<<16);
                lv.x = (u32)l0 | ((u32)l1<<16); lv.y = (u32)l2 | ((u32)l3<<16);
                int d = n*STR + (t*ICW + q*4)*2;
                *reinterpret_cast<uint2*>(Bh + d) = hv;
                *reinterpret_cast<uint2*>(Bl + d) = lv;
            }
        }
        __syncthreads();

        // ---- mma over K chunk (B resident, A streamed per-mt: low reg press) ----
#pragma unroll 1
        for (int ks = 0; ks < KC/16; ++ks) {
            const u32 kb2 = (u32)(ks * 32);   // kb*2 bytes
            u32 bh[2][4], bl[2][4];
#pragma unroll
            for (int g = 0; g < 2; ++g) {
                ldm4(bh[g], sbBh + boff + g*16*STR + kb2);
                ldm4(bl[g], sbBl + boff + g*16*STR + kb2);
            }
#pragma unroll
            for (int mt = 0; mt < 4; ++mt) {
                u32 ah[4], al[4];
                ldm4(ah, sbAh + aoff + mt*16*STR + kb2);
                ldm4(al, sbAl + aoff + mt*16*STR + kb2);
#pragma unroll
                for (int nt = 0; nt < 4; ++nt) {
                    const u32* bhp = &bh[nt>>1][(nt&1)*2];
                    const u32* blp = &bl[nt>>1][(nt&1)*2];
                    mma16816(D[mt][nt], ah, bhp);
                    mma16816(D[mt][nt], al, bhp);
                    mma16816(D[mt][nt], ah, blp);
                }
            }
        }
    }

    // ---- epilogue: bias + ReLU, NHWC store ----
    float bias2[4][2];
#pragma unroll
    for (int mt = 0; mt < 4; ++mt) {
        bias2[mt][0] = bias[wm*64 + mt*16 + (lane>>2)];
        bias2[mt][1] = bias[wm*64 + mt*16 + (lane>>2) + 8];
    }
    float* ob = &out[(((size_t)b*HH + y)*WW + x0)*HID];
#pragma unroll
    for (int mt = 0; mt < 4; ++mt)
#pragma unroll
        for (int nt = 0; nt < 4; ++nt)
#pragma unroll
            for (int r = 0; r < 4; ++r) {
                int m = wm*64 + mt*16 + (lane>>2) + ((r>>1)&1)*8;
                int n = wn*32 + nt*8 + (lane&3)*2 + (r&1);
                float v = D[mt][nt][r] + bias2[mt][(r>>1)&1];
                v = fmaxf(v, 0.f);
                ob[(size_t)n*HID + m] = v;
            }
}

// ---------------------------------------------------------------------------
// Final layer: NHWC 128 -> NCHW 6, SIMT. Block=(b,y), thread=pixel.
// ---------------------------------------------------------------------------
__global__ void __launch_bounds__(256, 1)
conv4(const float* __restrict__ in, const float* __restrict__ wgt,
      const float* __restrict__ bias, float* __restrict__ out)
{
    extern __shared__ float sm4[];
    float* ash = sm4;              // [3][258] x 33 floats (32 ic + pad)
    float* wsh = sm4 + 3*258*33;   // [6][128][5]

    const int b = blockIdx.x >> 8;
    const int y = blockIdx.x & 255;
    const int px = threadIdx.x;

    for (int i = threadIdx.x; i < 3840; i += 256) wsh[i] = wgt[i];

    float acc[6];
#pragma unroll
    for (int o = 0; o < 6; ++o) acc[o] = 0.f;

    for (int c = 0; c < 4; ++c) {
        __syncthreads();
        for (int idx = threadIdx.x; idx < 3*258*8; idx += 256) {
            int r = idx / (258*8), rem = idx % (258*8);
            int s = rem >> 3, kq = rem & 7;
            int yy = y + r - 1, xx = s - 1;
            float4 v = make_float4(0,0,0,0);
            if ((unsigned)yy < HH && (unsigned)xx < WW)
                v = *reinterpret_cast<const float4*>(
                    &in[(((size_t)b*HH + yy)*WW + xx)*HID + c*32 + kq*4]);
            float* d = &ash[(r*258 + s)*33 + kq*4];
            d[0] = v.x; d[1] = v.y; d[2] = v.z; d[3] = v.w;
        }
        __syncthreads();

        const float* au = &ash[(0*258 + px + 1)*33];
        const float* ac = &ash[(1*258 + px + 1)*33];
        const float* ad = &ash[(2*258 + px + 1)*33];
        const float* al = &ash[(1*258 + px + 0)*33];
        const float* ar = &ash[(1*258 + px + 2)*33];
#pragma unroll 4
        for (int k = 0; k < 32; ++k) {
            float vc = ac[k], vu = au[k], vd = ad[k], vl = al[k], vr = ar[k];
            const float* wp = &wsh[(c*32 + k)*5];
#pragma unroll
            for (int o = 0; o < 6; ++o) {
                const float* w = wp + o*640;
                float s = acc[o];
                s = fmaf(w[0], vc, s);
                s = fmaf(w[1], vu, s);
                s = fmaf(w[2], vd, s);
                s = fmaf(w[3], vl, s);
                s = fmaf(w[4], vr, s);
                acc[o] = s;
            }
        }
    }

#pragma unroll
    for (int o = 0; o < 6; ++o)
        out[(((size_t)b*6 + o)*HH + y)*WW + px] = acc[o] + bias[o];
}

extern "C" void kernel_launch(void* const* d_in, const int* in_sizes, int n_in,
                              void* d_out, int out_size)
{
    const float* x  = (const float*)d_in[0];
    const float* w1 = (const float*)d_in[1];
    const float* b1 = (const float*)d_in[2];
    const float* w2 = (const float*)d_in[3];
    const float* b2 = (const float*)d_in[4];
    const float* w3 = (const float*)d_in[5];
    const float* b3 = (const float*)d_in[6];
    const float* w4 = (const float*)d_in[7];
    const float* b4 = (const float*)d_in[8];
    float* out = (float*)d_out;

    float *act1, *act2; u16 *wh, *wl;
    cudaGetSymbolAddress((void**)&act1, g_act1);
    cudaGetSymbolAddress((void**)&act2, g_act2);
    cudaGetSymbolAddress((void**)&wh,   g_wh);
    cudaGetSymbolAddress((void**)&wl,   g_wl);

    const int smemL1  = 4*128*112;    // 57344
    const int smemMid = 4*128*176;    // 90112 -> 2 CTAs/SM
    const int smem4   = (3*258*33 + 3840) * 4;

    cudaFuncSetAttribute((const void*)conv_mma<8, 1, true, 2>,
                         cudaFuncAttributeMaxDynamicSharedMemorySize, smemL1);
    cudaFuncSetAttribute((const void*)conv_mma<16, 8, false, 2>,
                         cudaFuncAttributeMaxDynamicSharedMemorySize, smemMid);
    cudaFuncSetAttribute((const void*)conv4,
                         cudaFuncAttributeMaxDynamicSharedMemorySize, smem4);

    prep<<<660, 256>>>(w1, w2, w3);
    conv_mma<8, 1, true, 2 ><<<BB*HH*2, 256, smemL1 >>>(x,    wh,         wl,         b1, act1);
    conv_mma<16, 8, false, 2><<<BB*HH*2, 256, smemMid>>>(act1, wh + 5120,  wl + 5120,  b2, act2);
    conv_mma<16, 8, false, 2><<<BB*HH*2, 256, smemMid>>>(act2, wh + 87040, wl + 87040, b3, act1);
    conv4<<<BB*HH, 256, smem4>>>(act1, w4, b4, out);
}

// round 16
// speedup vs baseline: 3.4062x; 1.2958x over previous
#include <cuda_runtime.h>
#include <cuda_bf16.h>
#include <cstdint>

typedef unsigned int u32; typedef unsigned short u16; typedef unsigned long long u64;

#define BB 8
#define HH 256
#define WW 256

// ---- chunked activation layout: [b][c][y][x][ hi 32B | lo 32B | pad 16B ] ----
#define PXB 80            // bytes per pixel slot
#define ROWB (136*PXB)    // staged row: 136 px window = 10880 B
#define BREG (3*ROWB)     // 32640
#define WSTR 176          // weight smem row stride (160B data + 16 pad)
#define WPLANE (128*WSTR) // 22528
#define WREG (2*WPLANE)   // 45056
#define BUFB (BREG + WREG)        // 77696
#define SM_MBAR (2*BUFB)          // 155392
#define SMEM_MID (SM_MBAR + 32)
#define TXB (3*10560 + WREG)      // 76736 bytes per buffer fill

__device__ unsigned char g_act0[(size_t)BB*1*HH*WW*PXB];   // 40 MB  (layer-1 input,  1 chunk)
__device__ unsigned char g_act1[(size_t)BB*8*HH*WW*PXB];   // 320 MB (8 chunks)
__device__ unsigned char g_act2[(size_t)BB*8*HH*WW*PXB];   // 320 MB
__device__ unsigned char g_wm[17*WREG];                    // ldmatrix-ready weights (17 chunk-blocks)
__device__ unsigned char g_zero[10560];                    // zero row for OOB bulk src

static __device__ __forceinline__ u32 s2u(const void* p){
    u32 a; asm("{ .reg .u64 t; cvta.to.shared.u64 t, %1; cvt.u32.u64 %0, t; }":"=r"(a):"l"(p)); return a;}

static __device__ __forceinline__ void ldm4(u32* r, u32 addr){
    asm volatile("ldmatrix.sync.aligned.m8n8.x4.shared.b16 {%0,%1,%2,%3}, [%4];"
        : "=r"(r[0]),"=r"(r[1]),"=r"(r[2]),"=r"(r[3]) : "r"(addr));}

static __device__ __forceinline__ void mma16816(float* d, const u32* a, const u32* b){
    asm volatile("mma.sync.aligned.m16n8k16.row.col.f32.bf16.bf16.f32 "
        "{%0,%1,%2,%3}, {%4,%5,%6,%7}, {%8,%9}, {%0,%1,%2,%3};"
        : "+f"(d[0]),"+f"(d[1]),"+f"(d[2]),"+f"(d[3])
        : "r"(a[0]),"r"(a[1]),"r"(a[2]),"r"(a[3]), "r"(b[0]),"r"(b[1]));}

static __device__ __forceinline__ void split_bf16(float v, u16& h, u16& l){
    __nv_bfloat16 hb = __float2bfloat16(v);
    float r = v - __bfloat162float(hb);
    __nv_bfloat16 lb = __float2bfloat16(r);
    h = __bfloat16_as_ushort(hb);
    l = __bfloat16_as_ushort(lb);
}

static __device__ __forceinline__ void mbar_init(u32 m, u32 cnt){
    asm volatile("mbarrier.init.shared.b64 [%0], %1;" :: "r"(m), "r"(cnt) : "memory");}
static __device__ __forceinline__ void mbar_expect(u32 m, u32 tx){
    asm volatile("mbarrier.arrive.expect_tx.shared.b64 _, [%0], %1;" :: "r"(m), "r"(tx) : "memory");}
static __device__ __forceinline__ void bulk_g2s(u32 dst, const void* src, u32 sz, u32 mbar){
    asm volatile("cp.async.bulk.shared::cta.global.mbarrier::complete_tx::bytes [%0], [%1], %2, [%3];"
                 :: "r"(dst), "l"(src), "r"(sz), "r"(mbar) : "memory");}
static __device__ __forceinline__ void waitp(u32 m, u32 ph){
    u32 done;
    asm volatile("{\n\t.reg .pred p;\n\t"
        "mbarrier.try_wait.parity.acquire.cta.shared::cta.b64 p,[%1],%2;\n\t"
        "selp.b32 %0,1,0,p;\n\t}":"=r"(done):"r"(m),"r"(ph):"memory");
    while(!done){
        asm volatile("{\n\t.reg .pred p;\n\t"
            "mbarrier.try_wait.parity.acquire.cta.shared::cta.b64 p,[%1],%2,0x989680;\n\t"
            "selp.b32 %0,1,0,p;\n\t}":"=r"(done):"r"(m),"r"(ph):"memory");}}

// ---------------------------------------------------------------------------
// prep_w: bake split weights into ldmatrix-ready layout
// block b: 0 = L1 (16-ic padded from 6), 1..8 = L2 chunks, 9..16 = L3 chunks
// g_wm[blk][plane][oc][t*32 + icl*2]
// ---------------------------------------------------------------------------
__global__ void prep_w(const float* __restrict__ w1, const float* __restrict__ w2,
                       const float* __restrict__ w3)
{
    int i = blockIdx.x * 256 + threadIdx.x;
    if (i >= 17*10240) return;
    int blk = i / 10240, r = i % 10240;
    int oc = r / 80, r2 = r % 80, t = r2 / 16, icl = r2 % 16;
    float v;
    if (blk == 0)        v = (icl < 6) ? w1[(oc*6 + icl)*5 + t] : 0.f;
    else if (blk <= 8)   v = w2[(oc*128 + (blk-1)*16 + icl)*5 + t];
    else                 v = w3[(oc*128 + (blk-9)*16 + icl)*5 + t];
    u16 h, l; split_bf16(v, h, l);
    size_t base = (size_t)blk*WREG + (size_t)oc*WSTR + t*32 + icl*2;
    *reinterpret_cast<u16*>(g_wm + base)          = h;
    *reinterpret_cast<u16*>(g_wm + base + WPLANE) = l;
}

// ---------------------------------------------------------------------------
// prep_x: fp32 NCHW 6ch -> chunked plane layout (1 chunk, ic 6..15 zero)
// ---------------------------------------------------------------------------
__global__ void prep_x(const float* __restrict__ x)
{
    int i = blockIdx.x * 256 + threadIdx.x;   // 524288 px
    int b = i >> 16, y = (i >> 8) & 255, xx = i & 255;
    u32 hw[4] = {0,0,0,0}, lw[4] = {0,0,0,0};
#pragma unroll
    for (int ic = 0; ic < 6; ++ic) {
        float v = x[((size_t)(b*6 + ic)*HH + y)*WW + xx];
        u16 h, l; split_bf16(v, h, l);
        if (ic & 1) { hw[ic>>1] |= (u32)h << 16; lw[ic>>1] |= (u32)l << 16; }
        else        { hw[ic>>1] |= (u32)h;       lw[ic>>1] |= (u32)l; }
    }
    unsigned char* d = g_act0 + ((size_t)(b*HH + y)*WW + xx)*PXB;
    *reinterpret_cast<uint4*>(d +  0) = make_uint4(hw[0],hw[1],hw[2],hw[3]);
    *reinterpret_cast<uint4*>(d + 16) = make_uint4(0,0,0,0);
    *reinterpret_cast<uint4*>(d + 32) = make_uint4(lw[0],lw[1],lw[2],lw[3]);
    *reinterpret_cast<uint4*>(d + 48) = make_uint4(0,0,0,0);
    *reinterpret_cast<uint4*>(d + 64) = make_uint4(0,0,0,0);
}

// ---------------------------------------------------------------------------
// conv_mma: D[128oc,128px] via 3-pass bf16 split; bulk-async staged,
// double-buffered; tap shifts folded into ldmatrix lane addresses.
// ---------------------------------------------------------------------------
template <int CHIN, int CHUNKS>
__global__ void __launch_bounds__(256, 1)
conv_mma(const unsigned char* __restrict__ in, const unsigned char* __restrict__ wb,
         const float* __restrict__ bias, unsigned char* __restrict__ out)
{
    extern __shared__ char smc[];
    const u32 sb = s2u(smc);

    const int tid = threadIdx.x;
    const int warp = tid >> 5, lane = tid & 31;
    const int wm = warp >> 2, wn = warp & 3;

    const int bi = blockIdx.x;
    const int b  = bi >> 9;
    const int y  = (bi >> 1) & 255;
    const int x0 = (bi & 1) * 128;

    const int dstoff = (x0 == 0) ? 4*PXB : 0;   // valid px start in window
    const int xsrc   = (x0 == 0) ? 0 : 124;     // global x of first copied px
    const int pz     = (x0 == 0) ? 0 : 132;     // 4 OOB px slots to zero

    if (tid == 0) { mbar_init(sb + SM_MBAR, 1); mbar_init(sb + SM_MBAR + 8, 1); }
    __syncthreads();

    // issue chunk c into buffer p
    auto issue = [&](int c, int p) {
        const u32 mb = sb + SM_MBAR + p*8;
        mbar_expect(mb, TXB);
        const u32 bd = sb + p*BUFB;
#pragma unroll
        for (int r = 0; r < 3; ++r) {
            int yp = y - 1 + r;
            const unsigned char* src = ((unsigned)yp < HH)
                ? in + ((size_t)((b*CHIN + c)*HH + yp)*WW + xsrc)*PXB
                : g_zero;
            bulk_g2s(bd + r*ROWB + dstoff, src, 10560, mb);
        }
        bulk_g2s(bd + BREG, wb + (size_t)c*WREG, WREG, mb);
    };

    if (tid == 0) issue(0, 0);

    float D[4][4][4];
#pragma unroll
    for (int mt = 0; mt < 4; ++mt)
#pragma unroll
        for (int nt = 0; nt < 4; ++nt)
#pragma unroll
            for (int r = 0; r < 4; ++r) D[mt][nt][r] = 0.f;

    const u32 rnoff = (u32)((4 + wn*32 + ((lane>>4)&1)*8 + (lane&7))*PXB
                            + ((lane>>3)&1)*16);
    const u32 aoff  = (u32)(BREG + (wm*64 + (lane&15))*WSTR + ((lane>>4)&1)*16);

#pragma unroll 1
    for (int c = 0; c < CHUNKS; ++c) {
        const int p = c & 1;
        __syncthreads();                          // all warps done with buf p^1
        if (tid == 0 && c + 1 < CHUNKS) issue(c + 1, p ^ 1);
        waitp(sb + SM_MBAR + p*8, (c >> 1) & 1);
        if (tid < 48) {                           // zero 4 OOB px (3 rows x 4 px x 64B)
            int r = tid >> 4, i2 = (tid >> 2) & 3, q = tid & 3;
            *reinterpret_cast<uint4*>(smc + p*BUFB + r*ROWB + (pz + i2)*PXB + q*16)
                = make_uint4(0,0,0,0);
        }
        __syncthreads();

        const u32 bufb = sb + p*BUFB;
        const u32 Bln = bufb + rnoff;
        const u32 Aln = bufb + aoff;
#pragma unroll
        for (int t = 0; t < 5; ++t) {
            const int dy = (t==1) ? -1 : (t==2) ? 1 : 0;
            const int dx = (t==3) ? -1 : (t==4) ? 1 : 0;
            const u32 bbase = Bln + (1+dy)*ROWB + dx*PXB;
            u32 bh0[4], bh1[4], bl0[4], bl1[4];
            ldm4(bh0, bbase);
            ldm4(bh1, bbase + 16*PXB);
            ldm4(bl0, bbase + 32);
            ldm4(bl1, bbase + 32 + 16*PXB);
#pragma unroll
            for (int mt = 0; mt < 4; ++mt) {
                u32 ah[4], al[4];
                const u32 aa = Aln + mt*(16*WSTR) + t*32;
                ldm4(ah, aa);
                ldm4(al, aa + WPLANE);
#pragma unroll
                for (int nt = 0; nt < 4; ++nt) {
                    const u32* bhp = (nt < 2) ? &bh0[(nt&1)*2] : &bh1[(nt&1)*2];
                    const u32* blp = (nt < 2) ? &bl0[(nt&1)*2] : &bl1[(nt&1)*2];
                    mma16816(D[mt][nt], ah, bhp);
                    mma16816(D[mt][nt], al, bhp);
                    mma16816(D[mt][nt], ah, blp);
                }
            }
        }
    }

    // ---- epilogue: bias + ReLU, split, smem transpose, coalesced store ----
    float bias2[4][2];
#pragma unroll
    for (int mt = 0; mt < 4; ++mt) {
        bias2[mt][0] = bias[wm*64 + mt*16 + (lane>>2)];
        bias2[mt][1] = bias[wm*64 + mt*16 + (lane>>2) + 8];
    }
    __syncthreads();   // buffers free for reuse
#pragma unroll
    for (int mt = 0; mt < 4; ++mt)
#pragma unroll
        for (int nt = 0; nt < 4; ++nt)
#pragma unroll
            for (int r = 0; r < 4; ++r) {
                int m = wm*64 + mt*16 + (lane>>2) + ((r>>1)&1)*8;
                int n = wn*32 + nt*8 + (lane&3)*2 + (r&1);
                float v = D[mt][nt][r] + bias2[mt][(r>>1)&1];
                v = fmaxf(v, 0.f);
                u16 h, l; split_bf16(v, h, l);
                *reinterpret_cast<u16*>(smc + (size_t)n*256 + m*2)         = h;
                *reinterpret_cast<u16*>(smc + 32768 + (size_t)n*256 + m*2) = l;
            }
    __syncthreads();
    for (int idx = tid; idx < 4096; idx += 256) {
        int plane = idx >> 11, r2 = idx & 2047;
        int px = r2 >> 4, w = r2 & 15, cout = w >> 1, q = w & 1;
        uint4 v = *reinterpret_cast<const uint4*>(
            smc + plane*32768 + (size_t)px*256 + cout*32 + q*16);
        *reinterpret_cast<uint4*>(
            out + ((size_t)((b*8 + cout)*HH + y)*WW + (x0 + px))*PXB + plane*32 + q*16) = v;
    }
}

// ---------------------------------------------------------------------------
// conv4: chunked plane 128ic -> NCHW 6 fp32, SIMT. Block=(b,y), thread=pixel.
// ---------------------------------------------------------------------------
__global__ void __launch_bounds__(256, 1)
conv4(const unsigned char* __restrict__ in, const float* __restrict__ wgt,
      const float* __restrict__ bias, float* __restrict__ out)
{
    extern __shared__ float sm4[];
    float* ash = sm4;              // [3][258][17]  (16 ic + pad)
    float* wsh = sm4 + 3*258*17;   // [6][128][5]

    const int b = blockIdx.x >> 8;
    const int y = blockIdx.x & 255;
    const int px = threadIdx.x;

    for (int i = threadIdx.x; i < 3840; i += 256) wsh[i] = wgt[i];

    float acc[6];
#pragma unroll
    for (int o = 0; o < 6; ++o) acc[o] = 0.f;

    for (int c = 0; c < 8; ++c) {
        __syncthreads();
        for (int idx = threadIdx.x; idx < 3*258*2; idx += 256) {
            int r = idx / 516, rem = idx % 516, s = rem >> 1, q = rem & 1;
            int yy = y + r - 1, xx = s - 1;
            float* d = &ash[(r*258 + s)*17 + q*8];
            if ((unsigned)yy < HH && (unsigned)xx < WW) {
                const unsigned char* base =
                    in + ((size_t)((b*8 + c)*HH + yy)*WW + xx)*PXB + q*16;
                uint4 hv = *reinterpret_cast<const uint4*>(base);
                uint4 lv = *reinterpret_cast<const uint4*>(base + 32);
                const u32 hvv[4] = {hv.x, hv.y, hv.z, hv.w};
                const u32 lvv[4] = {lv.x, lv.y, lv.z, lv.w};
#pragma unroll
                for (int k = 0; k < 4; ++k) {
                    d[2*k]   = __bfloat162float(__ushort_as_bfloat16((u16)(hvv[k] & 0xFFFF)))
                             + __bfloat162float(__ushort_as_bfloat16((u16)(lvv[k] & 0xFFFF)));
                    d[2*k+1] = __bfloat162float(__ushort_as_bfloat16((u16)(hvv[k] >> 16)))
                             + __bfloat162float(__ushort_as_bfloat16((u16)(lvv[k] >> 16)));
                }
            } else {
#pragma unroll
                for (int k = 0; k < 8; ++k) d[k] = 0.f;
            }
        }
        __syncthreads();

        const float* au = &ash[(0*258 + px + 1)*17];
        const float* ac = &ash[(1*258 + px + 1)*17];
        const float* ad = &ash[(2*258 + px + 1)*17];
        const float* al = &ash[(1*258 + px + 0)*17];
        const float* ar = &ash[(1*258 + px + 2)*17];
#pragma unroll 4
        for (int k = 0; k < 16; ++k) {
            float vc = ac[k], vu = au[k], vd = ad[k], vl = al[k], vr = ar[k];
            const float* wp = &wsh[(c*16 + k)*5];
#pragma unroll
            for (int o = 0; o < 6; ++o) {
                const float* w = wp + o*640;
                float s = acc[o];
                s = fmaf(w[0], vc, s);
                s = fmaf(w[1], vu, s);
                s = fmaf(w[2], vd, s);
                s = fmaf(w[3], vl, s);
                s = fmaf(w[4], vr, s);
                acc[o] = s;
            }
        }
    }

#pragma unroll
    for (int o = 0; o < 6; ++o)
        out[((size_t)(b*6 + o)*HH + y)*WW + px] = acc[o] + bias[o];
}

extern "C" void kernel_launch(void* const* d_in, const int* in_sizes, int n_in,
                              void* d_out, int out_size)
{
    const float* x  = (const float*)d_in[0];
    const float* w1 = (const float*)d_in[1];
    const float* b1 = (const float*)d_in[2];
    const float* w2 = (const float*)d_in[3];
    const float* b2 = (const float*)d_in[4];
    const float* w3 = (const float*)d_in[5];
    const float* b3 = (const float*)d_in[6];
    const float* w4 = (const float*)d_in[7];
    const float* b4 = (const float*)d_in[8];
    float* out = (float*)d_out;

    unsigned char *a0, *a1, *a2, *wm;
    cudaGetSymbolAddress((void**)&a0, g_act0);
    cudaGetSymbolAddress((void**)&a1, g_act1);
    cudaGetSymbolAddress((void**)&a2, g_act2);
    cudaGetSymbolAddress((void**)&wm, g_wm);

    const int smem4 = (3*258*17 + 3840) * 4;   // 67992

    cudaFuncSetAttribute((const void*)conv_mma<1, 1>,
                         cudaFuncAttributeMaxDynamicSharedMemorySize, SMEM_MID);
    cudaFuncSetAttribute((const void*)conv_mma<8, 8>,
                         cudaFuncAttributeMaxDynamicSharedMemorySize, SMEM_MID);
    cudaFuncSetAttribute((const void*)conv4,
                         cudaFuncAttributeMaxDynamicSharedMemorySize, smem4);

    prep_w<<<680, 256>>>(w1, w2, w3);
    prep_x<<<2048, 256>>>(x);
    conv_mma<1, 1><<<BB*HH*2, 256, SMEM_MID>>>(a0, wm,            b1, a1);
    conv_mma<8, 8><<<BB*HH*2, 256, SMEM_MID>>>(a1, wm + 1*WREG,   b2, a2);
    conv_mma<8, 8><<<BB*HH*2, 256, SMEM_MID>>>(a2, wm + 9*WREG,   b3, a1);
    conv4<<<BB*HH, 256, smem4>>>(a1, w4, b4, out);
}